// round 11
// baseline (speedup 1.0000x reference)
#include <cuda_runtime.h>
#include <cstdint>

// Problem constants:
//   B=8, H=8, L=1024, D=64, K=49
//   x:  (B,H,L,D) fp32   = d_in[0]
//   W:  (H,D,K)   fp32   = d_in[1]
//   rp: (L,L)     int32  = d_in[2]
//   out:(B,H,L,L) fp32
// Separable structure: i = row_i*32 + col_i, j = rj*32 + cj,
//   rp[i][j] = 7*(pw(row_i-rj)+3) + (pw(col_i-cj)+3), pw in [-3,3].
#define BB 8
#define HH 8
#define LL 1024
#define DD 64
#define KK 49
#define BH (BB*HH)

#define WT_STRIDE 66       // Wt row pad: <=2-way bank conflict on LDS.64
#define IPB 8              // i-rows per block (one per warp)

// ---------------------------------------------------------------------------
// Fused kernel v8: v7's d-pair FFMA2 compute (conflict-free natural-x staging)
//                + v6's uniform separable gather (proven fast).
//
// Block (i-group, h): 8 warps; warp w owns i = i0+w and ALL 8 b's.
//   compute: acc0[b] = d-pair packed partial sums for k0=lane,
//            acc1[b] for k1=min(lane+32,48) (junk lanes>=17 discarded);
//            x: broadcast LDS.128 from natural layout; W: k-major Wt LDS.64.
//   gather:  spill lt -> warp-local smem; per rj: 1 shfl + per b:
//            broadcast LDS.32 (<=7 distinct banks) + coalesced STG.32.
// grid: (L/8, H) = (128, 8), block: 256.
// ---------------------------------------------------------------------------
__global__ __launch_bounds__(256, 5) void irpe_fused8_kernel(
    const float* __restrict__ x, const float* __restrict__ W,
    const int* __restrict__ rp, float* __restrict__ out)
{
    const int h    = blockIdx.y;
    const int i0   = blockIdx.x * IPB;
    const int tid  = threadIdx.x;
    const int w    = tid >> 5;
    const int lane = tid & 31;
    const int i    = i0 + w;
    const int row_i = i >> 5;
    const int col_i = i & 31;

    __shared__ float Wt[KK * WT_STRIDE + 2];      // k-major, ~12.9 KB
    __shared__ float xs[IPB * BB * DD];           // natural [w][b][d], 16 KB
    __shared__ float lts[IPB * BB * KK];          // [w][b][k], 12.25 KB

    // Separable index extraction (two tiny rp reads per warp)
    const int cidx  = rp[(size_t)i * LL + row_i * 32 + lane] - 21;  // in [0,6]
    const int rbase = rp[(size_t)i * LL + lane * 32 + col_i] - 3;   // 7*r, lane=rj

    // Stage W[h] transposed k-major: Wt[k*66 + d] = W[h][d][k]
    {
        const float* Wh = W + (size_t)h * DD * KK;
        #pragma unroll
        for (int t = tid; t < DD * KK; t += 256) {
            const int d = t / KK;
            const int k = t - d * KK;
            Wt[k * WT_STRIDE + d] = Wh[t];
        }
    }

    // Stage x natural (fully coalesced, conflict-free float4 copy):
    // xs[(w*8+b)*64 + d] = x[(b*8+h)][i0+w][d]
    #pragma unroll
    for (int t = tid; t < IPB * BB * (DD / 4); t += 256) {
        const int ww = t >> 7;
        const int b  = (t >> 4) & 7;
        const int q  = t & 15;
        float4 v = *(const float4*)(x + ((size_t)(b * HH + h) * LL + i0 + ww) * DD + q * 4);
        *(float4*)(xs + ((ww * BB + b) * DD) + q * 4) = v;
    }
    __syncthreads();

    // Compute: d-pair packed accumulators.
    //   acc0[b] = { sum_{d even} x[d]W[d][k0], sum_{d odd} ... },  k0 = lane
    //   acc1[b] = same for k1 = min(lane+32, 48)
    unsigned long long acc0[BB], acc1[BB];
    #pragma unroll
    for (int b = 0; b < BB; b++) { acc0[b] = 0ull; acc1[b] = 0ull; }

    const int k1 = (lane + 32 < KK) ? lane + 32 : KK - 1;
    const float* pW0 = Wt + lane * WT_STRIDE;
    const float* pW1 = Wt + k1 * WT_STRIDE;
    const float* xwp = xs + (w * BB) * DD;

    #pragma unroll 4
    for (int c = 0; c < 16; c++) {               // 4 d's per chunk
        unsigned long long w00, w01, w10, w11;
        w00 = *(const unsigned long long*)(pW0 + 4 * c);
        w01 = *(const unsigned long long*)(pW0 + 4 * c + 2);
        w10 = *(const unsigned long long*)(pW1 + 4 * c);
        w11 = *(const unsigned long long*)(pW1 + 4 * c + 2);
        #pragma unroll
        for (int b = 0; b < BB; b++) {
            const ulonglong2 xq = ((const ulonglong2*)(xwp + b * DD))[c];  // broadcast LDS.128
            asm("fma.rn.f32x2 %0, %1, %2, %0;" : "+l"(acc0[b]) : "l"(xq.x), "l"(w00));
            asm("fma.rn.f32x2 %0, %1, %2, %0;" : "+l"(acc0[b]) : "l"(xq.y), "l"(w01));
            asm("fma.rn.f32x2 %0, %1, %2, %0;" : "+l"(acc1[b]) : "l"(xq.x), "l"(w10));
            asm("fma.rn.f32x2 %0, %1, %2, %0;" : "+l"(acc1[b]) : "l"(xq.y), "l"(w11));
        }
    }

    // Finalize (merge even/odd-d halves) and spill to warp-local smem.
    float* lw = lts + w * (BB * KK);
    #pragma unroll
    for (int b = 0; b < BB; b++) {
        float lo, hi;
        asm("mov.b64 {%0, %1}, %2;" : "=f"(lo), "=f"(hi) : "l"(acc0[b]));
        lw[b * KK + lane] = lo + hi;
    }
    if (lane < KK - 32) {
        #pragma unroll
        for (int b = 0; b < BB; b++) {
            float lo, hi;
            asm("mov.b64 {%0, %1}, %2;" : "=f"(lo), "=f"(hi) : "l"(acc1[b]));
            lw[b * KK + 32 + lane] = lo + hi;
        }
    }
    __syncwarp();

    // Gather + streaming stores (v6 uniform loop).
    // out[b*8+h][i][rj*32+lane] = lw[b*49 + rbase(rj) + cidx(lane)]
    const float* lwc = lw + cidx;
    float* ob = out + ((size_t)h * LL + i) * LL + lane;   // b=0 base
    #pragma unroll 4
    for (int rj = 0; rj < 32; rj++) {
        const int rb = __shfl_sync(0xffffffffu, rbase, rj);
        const float* src = lwc + rb;
        float* dst = ob + rj * 32;
        #pragma unroll
        for (int b = 0; b < BB; b++) {
            const float v = src[b * KK];                       // broadcast LDS
            __stcs(dst + (size_t)b * (HH * LL * LL), v);       // coalesced STG.32
        }
    }
}

// ---------------------------------------------------------------------------
extern "C" void kernel_launch(void* const* d_in, const int* in_sizes, int n_in,
                              void* d_out, int out_size)
{
    const float* x  = (const float*)d_in[0];
    const float* W  = (const float*)d_in[1];
    const int*   rp = (const int*)d_in[2];
    float*       out = (float*)d_out;

    dim3 grid(LL / IPB, HH);
    irpe_fused8_kernel<<<grid, 256>>>(x, W, rp, out);
}

// round 12
// speedup vs baseline: 1.2560x; 1.2560x over previous
#include <cuda_runtime.h>
#include <cstdint>

// Problem constants:
//   B=8, H=8, L=1024, D=64, K=49
//   x:  (B,H,L,D) fp32   = d_in[0]
//   W:  (H,D,K)   fp32   = d_in[1]
//   rp: (L,L)     int32  = d_in[2]
//   out:(B,H,L,L) fp32
// Separable structure: i = row_i*32 + col_i, j = rj*32 + cj,
//   rp[i][j] = 7*(pw(row_i-rj)+3) + (pw(col_i-cj)+3), pw in [-3,3].
#define BB 8
#define HH 8
#define LL 1024
#define DD 64
#define KK 49
#define BH (BB*HH)

#define IPB 8              // i-rows per block (one per warp)
#define XP 10              // padded xst row: 8 b's + 2 pad (rows 40B-aligned)

// ---------------------------------------------------------------------------
// Fused kernel v9 = v6 with staging conflicts fixed.
//
// Block (i-group, h): 8 warps; warp w owns i = i0+w and ALL 8 b's.
//   compute: acc[bp]   = { lt[2bp][lane],   lt[2bp+1][lane]   }  (f32x2)
//            acc[4+bp] = { lt[2bp][lane+32], lt[2bp+1][lane+32] } (lanes<17)
//            W: Ws stride-49, conflict-free scalar LDS;
//            x: xst[w][d][b] rows padded to 10 -> staging 4-way (was 16-way),
//               compute reads 4 broadcast LDS.64 per d.
//   gather:  spill lt -> warp-local smem; per rj: 1 shfl + per b:
//            broadcast LDS.32 (<=7 banks) + coalesced STG.32 (v6, proven).
// grid: (L/8, H) = (128, 8), block: 256.
// ---------------------------------------------------------------------------
__global__ __launch_bounds__(256, 5) void irpe_fused9_kernel(
    const float* __restrict__ x, const float* __restrict__ W,
    const int* __restrict__ rp, float* __restrict__ out)
{
    const int h    = blockIdx.y;
    const int i0   = blockIdx.x * IPB;
    const int tid  = threadIdx.x;
    const int w    = tid >> 5;
    const int lane = tid & 31;
    const int i    = i0 + w;
    const int row_i = i >> 5;
    const int col_i = i & 31;

    __shared__ float Ws[DD * KK + 32];            // 12.7 KB, natural layout
    __shared__ float xst[IPB * DD * XP];          // [w][d][b(+pad)], 20 KB
    __shared__ float lts[IPB * BB * KK];          // [w][b][k], 12.25 KB

    // Separable index extraction (two tiny rp reads per warp)
    const int cidx  = rp[(size_t)i * LL + row_i * 32 + lane] - 21;  // in [0,6]
    const int rbase = rp[(size_t)i * LL + lane * 32 + col_i] - 3;   // 7*r, lane=rj

    // Stage W[h]: direct coalesced copy (reads use d*49+k addressing)
    {
        const float* Wh = W + (size_t)h * DD * KK;
        #pragma unroll
        for (int t = tid; t < DD * KK; t += 256)
            Ws[t] = Wh[t];
    }

    // Stage x transposed with padded rows: xst[(ww*64 + d)*10 + b]
    // 4-way max bank conflict (was 16-way unpadded).
    #pragma unroll
    for (int t = tid; t < IPB * BB * (DD / 4); t += 256) {
        const int ww = t >> 7;
        const int b  = (t >> 4) & 7;
        const int q  = t & 15;
        float4 v = *(const float4*)(x + ((size_t)(b * HH + h) * LL + i0 + ww) * DD + q * 4);
        float* dst = xst + (ww * DD + q * 4) * XP + b;
        dst[0 * XP] = v.x;
        dst[1 * XP] = v.y;
        dst[2 * XP] = v.z;
        dst[3 * XP] = v.w;
    }
    __syncthreads();

    // Compute lt for all 8 b (b-pairs packed in f32x2), v6 structure.
    unsigned long long acc[8];
    #pragma unroll
    for (int j = 0; j < 8; j++) acc[j] = 0ull;

    #pragma unroll 16
    for (int d = 0; d < DD; d++) {
        const float w0 = Ws[d * KK + lane];            // conflict-free
        const float w1 = Ws[d * KK + 32 + lane];       // junk lanes>=17, discarded
        unsigned long long wp0, wp1;
        asm("mov.b64 %0, {%1, %1};" : "=l"(wp0) : "f"(w0));
        asm("mov.b64 %0, {%1, %1};" : "=l"(wp1) : "f"(w1));
        const float* xr = xst + (w * DD + d) * XP;     // 8B-aligned row
        const unsigned long long xa = *(const unsigned long long*)(xr);      // {b0,b1}
        const unsigned long long xb = *(const unsigned long long*)(xr + 2);  // {b2,b3}
        const unsigned long long xc = *(const unsigned long long*)(xr + 4);  // {b4,b5}
        const unsigned long long xd = *(const unsigned long long*)(xr + 6);  // {b6,b7}
        asm("fma.rn.f32x2 %0, %1, %2, %0;" : "+l"(acc[0]) : "l"(xa), "l"(wp0));
        asm("fma.rn.f32x2 %0, %1, %2, %0;" : "+l"(acc[1]) : "l"(xb), "l"(wp0));
        asm("fma.rn.f32x2 %0, %1, %2, %0;" : "+l"(acc[2]) : "l"(xc), "l"(wp0));
        asm("fma.rn.f32x2 %0, %1, %2, %0;" : "+l"(acc[3]) : "l"(xd), "l"(wp0));
        asm("fma.rn.f32x2 %0, %1, %2, %0;" : "+l"(acc[4]) : "l"(xa), "l"(wp1));
        asm("fma.rn.f32x2 %0, %1, %2, %0;" : "+l"(acc[5]) : "l"(xb), "l"(wp1));
        asm("fma.rn.f32x2 %0, %1, %2, %0;" : "+l"(acc[6]) : "l"(xc), "l"(wp1));
        asm("fma.rn.f32x2 %0, %1, %2, %0;" : "+l"(acc[7]) : "l"(xd), "l"(wp1));
    }

    // Spill lt to warp-local smem region: lw[b*49 + k]
    float* lw = lts + w * (BB * KK);
    #pragma unroll
    for (int bp = 0; bp < 4; bp++) {
        float lo, hi;
        asm("mov.b64 {%0, %1}, %2;" : "=f"(lo), "=f"(hi) : "l"(acc[bp]));
        lw[(2 * bp)     * KK + lane] = lo;
        lw[(2 * bp + 1) * KK + lane] = hi;
        if (lane < KK - 32) {
            asm("mov.b64 {%0, %1}, %2;" : "=f"(lo), "=f"(hi) : "l"(acc[4 + bp]));
            lw[(2 * bp)     * KK + 32 + lane] = lo;
            lw[(2 * bp + 1) * KK + 32 + lane] = hi;
        }
    }
    __syncwarp();

    // Gather + streaming stores (v6 uniform loop).
    // out[b*8+h][i][rj*32+lane] = lw[b*49 + rbase(rj) + cidx(lane)]
    const float* lwc = lw + cidx;
    float* ob = out + ((size_t)h * LL + i) * LL + lane;   // b=0 base
    #pragma unroll 4
    for (int rj = 0; rj < 32; rj++) {
        const int rb = __shfl_sync(0xffffffffu, rbase, rj);
        const float* src = lwc + rb;
        float* dst = ob + rj * 32;
        #pragma unroll
        for (int b = 0; b < BB; b++) {
            const float v = src[b * KK];                       // broadcast LDS
            __stcs(dst + (size_t)b * (HH * LL * LL), v);       // coalesced STG.32
        }
    }
}

// ---------------------------------------------------------------------------
extern "C" void kernel_launch(void* const* d_in, const int* in_sizes, int n_in,
                              void* d_out, int out_size)
{
    const float* x  = (const float*)d_in[0];
    const float* W  = (const float*)d_in[1];
    const int*   rp = (const int*)d_in[2];
    float*       out = (float*)d_out;

    dim3 grid(LL / IPB, HH);
    irpe_fused9_kernel<<<grid, 256>>>(x, W, rp, out);
}

// round 13
// speedup vs baseline: 1.2617x; 1.0046x over previous
#include <cuda_runtime.h>
#include <cstdint>

// Problem constants:
//   B=8, H=8, L=1024, D=64, K=49
//   x:  (B,H,L,D) fp32   = d_in[0]
//   W:  (H,D,K)   fp32   = d_in[1]
//   rp: (L,L)     int32  = d_in[2]
//   out:(B,H,L,L) fp32
// Separable structure: i = row_i*32 + col_i, j = rj*32 + cj,
//   rp[i][j] = 7*(pw(row_i-rj)+3) + (pw(col_i-cj)+3), pw in [-3,3].
#define BB 8
#define HH 8
#define LL 1024
#define DD 64
#define KK 49
#define BH (BB*HH)

#define IPB 8              // i-rows per block (one per warp)
#define XP 10              // padded xst row: 8 b's + 2 pad (rows 40B-aligned)
#define WSLOT (DD * XP)    // 640 floats: per-warp region in the shared overlay

// ---------------------------------------------------------------------------
// Fused kernel v10 = v9 with xst/lts OVERLAY (warp-private aliasing).
//   xst[w] (640 floats) is dead once warp w's accumulators are computed;
//   warp w then spills its lt (392 floats) into the SAME region. No cross-warp
//   hazard (regions are warp-private), no extra syncs.
//   smem: 46 KB -> 33 KB  =>  residency 4 -> 5 blocks/SM (reg-bound).
//
// Block (i-group, h): 8 warps; warp w owns i = i0+w and ALL 8 b's.
//   compute: acc[bp]   = { lt[2bp][lane],   lt[2bp+1][lane]   }  (f32x2)
//            acc[4+bp] = { lt[2bp][lane+32], lt[2bp+1][lane+32] } (lanes<17)
//            W: Ws stride-49 natural, conflict-free scalar LDS;
//            x: padded-transposed rows, 4 broadcast LDS.64 per d.
//   gather:  per rj: 1 shfl + per b: broadcast LDS.32 (<=7 banks) + STG.32.
// grid: (L/8, H) = (128, 8), block: 256.
// ---------------------------------------------------------------------------
__global__ __launch_bounds__(256, 5) void irpe_fused10_kernel(
    const float* __restrict__ x, const float* __restrict__ W,
    const int* __restrict__ rp, float* __restrict__ out)
{
    const int h    = blockIdx.y;
    const int i0   = blockIdx.x * IPB;
    const int tid  = threadIdx.x;
    const int w    = tid >> 5;
    const int lane = tid & 31;
    const int i    = i0 + w;
    const int row_i = i >> 5;
    const int col_i = i & 31;

    __shared__ float Ws[DD * KK + 32];      // 12.7 KB, natural layout
    __shared__ float buf[IPB * WSLOT];      // 20 KB: xst, later aliased as lts

    // Separable index extraction (two tiny rp reads per warp)
    const int cidx  = rp[(size_t)i * LL + row_i * 32 + lane] - 21;  // in [0,6]
    const int rbase = rp[(size_t)i * LL + lane * 32 + col_i] - 3;   // 7*r, lane=rj

    // Stage W[h]: direct coalesced copy
    {
        const float* Wh = W + (size_t)h * DD * KK;
        #pragma unroll
        for (int t = tid; t < DD * KK; t += 256)
            Ws[t] = Wh[t];
    }

    // Stage x transposed with padded rows: buf[ww*640 + d*10 + b]
    #pragma unroll
    for (int t = tid; t < IPB * BB * (DD / 4); t += 256) {
        const int ww = t >> 7;
        const int b  = (t >> 4) & 7;
        const int q  = t & 15;
        float4 v = *(const float4*)(x + ((size_t)(b * HH + h) * LL + i0 + ww) * DD + q * 4);
        float* dst = buf + ww * WSLOT + (q * 4) * XP + b;
        dst[0 * XP] = v.x;
        dst[1 * XP] = v.y;
        dst[2 * XP] = v.z;
        dst[3 * XP] = v.w;
    }
    __syncthreads();

    // Compute lt for all 8 b (b-pairs packed in f32x2)
    unsigned long long acc[8];
    #pragma unroll
    for (int j = 0; j < 8; j++) acc[j] = 0ull;

    const float* xw = buf + w * WSLOT;
    #pragma unroll 16
    for (int d = 0; d < DD; d++) {
        const float w0 = Ws[d * KK + lane];            // conflict-free
        const float w1 = Ws[d * KK + 32 + lane];       // junk lanes>=17, discarded
        unsigned long long wp0, wp1;
        asm("mov.b64 %0, {%1, %1};" : "=l"(wp0) : "f"(w0));
        asm("mov.b64 %0, {%1, %1};" : "=l"(wp1) : "f"(w1));
        const float* xr = xw + d * XP;                 // 8B-aligned row
        const unsigned long long xa = *(const unsigned long long*)(xr);      // {b0,b1}
        const unsigned long long xb = *(const unsigned long long*)(xr + 2);  // {b2,b3}
        const unsigned long long xc = *(const unsigned long long*)(xr + 4);  // {b4,b5}
        const unsigned long long xd = *(const unsigned long long*)(xr + 6);  // {b6,b7}
        asm("fma.rn.f32x2 %0, %1, %2, %0;" : "+l"(acc[0]) : "l"(xa), "l"(wp0));
        asm("fma.rn.f32x2 %0, %1, %2, %0;" : "+l"(acc[1]) : "l"(xb), "l"(wp0));
        asm("fma.rn.f32x2 %0, %1, %2, %0;" : "+l"(acc[2]) : "l"(xc), "l"(wp0));
        asm("fma.rn.f32x2 %0, %1, %2, %0;" : "+l"(acc[3]) : "l"(xd), "l"(wp0));
        asm("fma.rn.f32x2 %0, %1, %2, %0;" : "+l"(acc[4]) : "l"(xa), "l"(wp1));
        asm("fma.rn.f32x2 %0, %1, %2, %0;" : "+l"(acc[5]) : "l"(xb), "l"(wp1));
        asm("fma.rn.f32x2 %0, %1, %2, %0;" : "+l"(acc[6]) : "l"(xc), "l"(wp1));
        asm("fma.rn.f32x2 %0, %1, %2, %0;" : "+l"(acc[7]) : "l"(xd), "l"(wp1));
    }

    // Spill lt into the SAME warp-private region (xst data now dead): lw[b*49+k]
    float* lw = buf + w * WSLOT;
    __syncwarp();   // all lanes of this warp done reading xst
    #pragma unroll
    for (int bp = 0; bp < 4; bp++) {
        float lo, hi;
        asm("mov.b64 {%0, %1}, %2;" : "=f"(lo), "=f"(hi) : "l"(acc[bp]));
        lw[(2 * bp)     * KK + lane] = lo;
        lw[(2 * bp + 1) * KK + lane] = hi;
        if (lane < KK - 32) {
            asm("mov.b64 {%0, %1}, %2;" : "=f"(lo), "=f"(hi) : "l"(acc[4 + bp]));
            lw[(2 * bp)     * KK + 32 + lane] = lo;
            lw[(2 * bp + 1) * KK + 32 + lane] = hi;
        }
    }
    __syncwarp();

    // Gather + streaming stores.
    // out[b*8+h][i][rj*32+lane] = lw[b*49 + rbase(rj) + cidx(lane)]
    const float* lwc = lw + cidx;
    float* dst = out + ((size_t)h * LL + i) * LL + lane;   // b=0, rj=0 base
    #pragma unroll 4
    for (int rj = 0; rj < 32; rj++) {
        const int rb = __shfl_sync(0xffffffffu, rbase, rj);
        const float* src = lwc + rb;
        #pragma unroll
        for (int b = 0; b < BB; b++) {
            const float v = src[b * KK];                       // broadcast LDS
            __stcs(dst + (size_t)b * (HH * LL * LL), v);       // coalesced STG.32
        }
        dst += 32;
    }
}

// ---------------------------------------------------------------------------
extern "C" void kernel_launch(void* const* d_in, const int* in_sizes, int n_in,
                              void* d_out, int out_size)
{
    const float* x  = (const float*)d_in[0];
    const float* W  = (const float*)d_in[1];
    const int*   rp = (const int*)d_in[2];
    float*       out = (float*)d_out;

    dim3 grid(LL / IPB, HH);
    irpe_fused10_kernel<<<grid, 256>>>(x, W, rp, out);
}